// round 2
// baseline (speedup 1.0000x reference)
#include <cuda_runtime.h>
#include <math_constants.h>
#include <math.h>

#define BB 32
#define NN 1024
#define FF 10
#define DD 64
#define MM 4
#define RR 8
#define KK 20
#define NROWS (BB*NN)           // 32768
#define BN_EPS 1e-5f

// ---------------- scratch (device globals; no runtime allocation) ----------------
__device__ float g_hit[NROWS*DD];        // h_it  [B,N,D]
__device__ float g_xlin[NROWS*DD];       // x_lin [B,N,D]
__device__ float g_eit[NROWS];           // e_it  [B,N]
__device__ float g_pih[BB*MM];           // pi_hard (forward value of pi_t)
__device__ float g_mixed[NROWS*DD];      // mixed [B,N,D]
__device__ float g_si[NROWS];
__device__ float g_sj[NROWS];
__device__ float g_scores[(size_t)BB*NN*NN];   // 128 MiB
__device__ float g_tv[NROWS*KK];
__device__ int   g_ti[NROWS*KK];
__device__ float g_gnn[NROWS*DD];
__device__ float g_y[NROWS*DD];
__device__ double g_stats[4*DD];         // sum1, sq1, sum2, sq2

// ---------------- helpers ----------------
__device__ __forceinline__ float nanfix(float x){
  if (isnan(x)) return 0.f;
  if (isinf(x)) return x > 0.f ? 1e4f : -1e4f;
  return x;
}
__device__ __forceinline__ float lrelu(float x){ return x >= 0.f ? x : 0.2f*x; }

__device__ __forceinline__ unsigned long long ffma2(unsigned long long a,
                                                    unsigned long long b,
                                                    unsigned long long c){
  unsigned long long d;
  asm("fma.rn.f32x2 %0, %1, %2, %3;" : "=l"(d) : "l"(a), "l"(b), "l"(c));
  return d;
}
__device__ __forceinline__ unsigned long long dup2(float a){
  unsigned long long r;
  asm("mov.b64 %0, {%1, %1};" : "=l"(r) : "f"(a));
  return r;
}
__device__ __forceinline__ void unpack2(unsigned long long v, float& lo, float& hi){
  asm("mov.b64 {%0, %1}, %2;" : "=f"(lo), "=f"(hi) : "l"(v));
}

// ---------------- K0: zero BN accumulators ----------------
__global__ void k_zero(){
  g_stats[threadIdx.x] = 0.0;
}

// ---------------- K1: cond MLP (h_it, e_it) + x_lin ----------------
__global__ void __launch_bounds__(64) k_cond(const float* __restrict__ data,
    const float* __restrict__ Wc, const float* __restrict__ bc,
    const float* __restrict__ Wap, const float* __restrict__ bap,
    const float* __restrict__ Wav, const float* __restrict__ Wg){
  int row = blockIdx.x;          // b*N + n
  int d = threadIdx.x;
  __shared__ float sd[FF];
  __shared__ float sh[DD];
  __shared__ float sr[DD];
  if (d < FF) sd[d] = data[row*FF + d];
  __syncthreads();
  float h = bc[d];
  float xl = 0.f;
  #pragma unroll
  for (int f = 0; f < FF; f++){
    float x = sd[f];
    h  = fmaf(x, Wc[f*DD + d], h);
    xl = fmaf(x, Wg[f*DD + d], xl);
  }
  sh[d] = h;
  g_hit[row*DD + d] = h;
  g_xlin[row*DD + d] = xl;
  __syncthreads();
  float a = bap[d];
  #pragma unroll 8
  for (int e = 0; e < DD; e++) a = fmaf(sh[e], Wap[e*DD + d], a);
  a = lrelu(a);
  sr[d] = a * Wav[d];
  __syncthreads();
  for (int s = 32; s > 0; s >>= 1){
    if (d < s) sr[d] += sr[d + s];
    __syncthreads();
  }
  if (d == 0) g_eit[row] = nanfix(sr[0]);
}

// ---------------- K2: pooling softmax + h_sys + gumbel top-2 routing ----------------
__global__ void __launch_bounds__(256) k_pool(const float* __restrict__ Wr,
    const float* __restrict__ br, const float* __restrict__ gum,
    float* __restrict__ hs_out, float* __restrict__ ps_out){
  int b = blockIdx.x, t = threadIdx.x;
  __shared__ float red[256];
  __shared__ float swv[NN];
  __shared__ float shs[DD];
  __shared__ float slog[MM];
  const float* e = g_eit + b*NN;
  float m = -CUDART_INF_F;
  for (int n = t; n < NN; n += 256) m = fmaxf(m, e[n]);
  red[t] = m; __syncthreads();
  for (int s = 128; s > 0; s >>= 1){ if (t < s) red[t] = fmaxf(red[t], red[t+s]); __syncthreads(); }
  float mx = red[0];
  __syncthreads();
  float se = 0.f;
  for (int n = t; n < NN; n += 256){ float w = expf(e[n] - mx); swv[n] = w; se += w; }
  red[t] = se; __syncthreads();
  for (int s = 128; s > 0; s >>= 1){ if (t < s) red[t] += red[t+s]; __syncthreads(); }
  float denom = red[0];
  __syncthreads();
  int d = t & 63, c = t >> 6;
  float acc = 0.f;
  for (int n = c; n < NN; n += 4)
    acc = fmaf(swv[n], g_hit[((size_t)b*NN + n)*DD + d], acc);
  red[t] = acc; __syncthreads();
  if (t < DD){
    float hs = (red[t] + red[t+64] + red[t+128] + red[t+192]) / denom;
    shs[t] = hs;
    hs_out[b*DD + t] = hs;
  }
  __syncthreads();
  if (t < MM){
    float lg = br[t] + gum[b*MM + t];   // TAU = 1
    #pragma unroll 8
    for (int dd2 = 0; dd2 < DD; dd2++) lg = fmaf(shs[dd2], Wr[dd2*MM + t], lg);
    slog[t] = lg;
  }
  __syncthreads();
  if (t == 0){
    float mm = slog[0];
    #pragma unroll
    for (int i = 1; i < MM; i++) mm = fmaxf(mm, slog[i]);
    float p[MM]; float s = 0.f;
    #pragma unroll
    for (int i = 0; i < MM; i++){ p[i] = expf(slog[i] - mm); s += p[i]; }
    #pragma unroll
    for (int i = 0; i < MM; i++){ p[i] /= s; ps_out[b*MM + i] = p[i]; }
    // top-2, ties -> lowest index first (strict >)
    int i1 = 0;
    #pragma unroll
    for (int i = 1; i < MM; i++) if (p[i] > p[i1]) i1 = i;
    int i2 = -1;
    #pragma unroll
    for (int i = 0; i < MM; i++){
      if (i == i1) continue;
      if (i2 < 0 || p[i] > p[i2]) i2 = i;
    }
    float nrm = fmaxf(p[i1] + p[i2], 1e-12f);
    #pragma unroll
    for (int i = 0; i < MM; i++) g_pih[b*MM + i] = 0.f;
    g_pih[b*MM + i1] = p[i1] / nrm;
    g_pih[b*MM + i2] = p[i2] / nrm;
  }
}

// ---------------- K3: mixed embeddings + s_i / s_j ----------------
__global__ void __launch_bounds__(64) k_mixed(const float* __restrict__ ebase,
    const float* __restrict__ lru, const float* __restrict__ lrv,
    const float* __restrict__ ai, const float* __restrict__ aj,
    const float* __restrict__ aei, const float* __restrict__ aej){
  int row = blockIdx.x;
  int b = row >> 10, n = row & (NN-1);
  int d = threadIdx.x;
  __shared__ float coef[MM*RR];
  __shared__ float spi[MM];
  __shared__ float r1[DD], r2[DD];
  if (d < MM) spi[d] = g_pih[b*MM + d];
  __syncthreads();
  if (d < MM*RR){
    int m = d >> 3, r = d & 7;
    coef[d] = spi[m] * lru[(m*NN + n)*RR + r];
  }
  __syncthreads();
  float sp = spi[0] + spi[1] + spi[2] + spi[3];
  float mx = sp * ebase[n*DD + d];
  #pragma unroll
  for (int c = 0; c < MM*RR; c++)
    mx = fmaf(coef[c], lrv[c*DD + d], mx);
  mx = nanfix(mx);
  g_mixed[row*DD + d] = mx;
  float xl = g_xlin[row*DD + d];
  r1[d] = xl*ai[d] + mx*aei[d];
  r2[d] = xl*aj[d] + mx*aej[d];
  __syncthreads();
  for (int s = 32; s > 0; s >>= 1){
    if (d < s){ r1[d] += r1[d+s]; r2[d] += r2[d+s]; }
    __syncthreads();
  }
  if (d == 0){ g_si[row] = r1[0]; g_sj[row] = r2[0]; }
}

// ---------------- K4: scores = mixed @ mixed^T (per batch), f32x2 GEMM ----------------
__global__ void __launch_bounds__(256) k_scores(){
  __shared__ float As[64][65];
  __shared__ float Bst[64][66];
  int b = blockIdx.z;
  int i0 = blockIdx.y * 64;
  int j0 = blockIdx.x * 64;
  int t = threadIdx.x;
  const float* A = g_mixed + ((size_t)b*NN + i0)*DD;
  const float* Bm = g_mixed + ((size_t)b*NN + j0)*DD;
  #pragma unroll
  for (int i = 0; i < 16; i++){
    int e = t + i*256;
    int r = e >> 6, k = e & 63;
    As[r][k] = A[e];
    Bst[k][r] = Bm[e];
  }
  __syncthreads();
  int tx = t & 15, ty = t >> 4;
  int ib = ty*4, jb = tx*4;
  unsigned long long acc[4][2];
  #pragma unroll
  for (int ii = 0; ii < 4; ii++){ acc[ii][0] = 0ull; acc[ii][1] = 0ull; }
  #pragma unroll 16
  for (int k = 0; k < 64; k++){
    unsigned long long b01 = *(const unsigned long long*)&Bst[k][jb];
    unsigned long long b23 = *(const unsigned long long*)&Bst[k][jb+2];
    #pragma unroll
    for (int ii = 0; ii < 4; ii++){
      unsigned long long a2 = dup2(As[ib+ii][k]);
      acc[ii][0] = ffma2(a2, b01, acc[ii][0]);
      acc[ii][1] = ffma2(a2, b23, acc[ii][1]);
    }
  }
  #pragma unroll
  for (int ii = 0; ii < 4; ii++){
    float v0,v1,v2,v3;
    unpack2(acc[ii][0], v0, v1);
    unpack2(acc[ii][1], v2, v3);
    float* C = g_scores + ((size_t)b*NN + (i0+ib+ii))*NN + j0 + jb;
    C[0]=v0; C[1]=v1; C[2]=v2; C[3]=v3;
  }
}

// ---------------- K5: top-20 per row (warp per row) ----------------
__global__ void __launch_bounds__(256) k_topk(){
  int warp = threadIdx.x >> 5;
  int lane = threadIdx.x & 31;
  int row = blockIdx.x*8 + warp;
  const float* srow = g_scores + (size_t)row*NN;
  float v[32];
  #pragma unroll
  for (int j = 0; j < 32; j++) v[j] = srow[j*32 + lane];
  // per-lane sorted top-3 (value desc, tie -> lower j first via strict >)
  float c0v=-CUDART_INF_F, c1v=-CUDART_INF_F, c2v=-CUDART_INF_F;
  int   c0j=0, c1j=0, c2j=0;
  #pragma unroll
  for (int j = 0; j < 32; j++){
    float x = v[j];
    if (x > c2v){
      if (x > c1v){
        c2v=c1v; c2j=c1j;
        if (x > c0v){ c1v=c0v; c1j=c0j; c0v=x; c0j=j; }
        else        { c1v=x; c1j=j; }
      } else { c2v=x; c2j=j; }
    }
  }
  unsigned used = 0u;
  int p = 0;
  float candv = c0v; int candg = c0j*32 + lane;
  float* otv = g_tv + row*KK;
  int*   oti = g_ti + row*KK;
  for (int k = 0; k < KK; k++){
    float bv = candv; int bg = candg;
    #pragma unroll
    for (int off = 16; off > 0; off >>= 1){
      float ov = __shfl_xor_sync(0xffffffffu, bv, off);
      int   og = __shfl_xor_sync(0xffffffffu, bg, off);
      if (ov > bv || (ov == bv && og < bg)){ bv = ov; bg = og; }
    }
    if (lane == 0){ otv[k] = bv; oti[k] = bg; }
    if ((bg & 31) == lane && bv == candv && bg == candg){
      used |= 1u << (bg >> 5);
      p++;
      if (p == 1){ candv = c1v; candg = c1j*32 + lane; }
      else if (p == 2){ candv = c2v; candg = c2j*32 + lane; }
      else {
        candv = -CUDART_INF_F; candg = 0x7fffffff;
        #pragma unroll
        for (int j = 0; j < 32; j++){
          if (!((used >> j) & 1u)){
            float x = v[j];
            if (x > candv){ candv = x; candg = j*32 + lane; }
          }
        }
      }
    }
  }
}

// ---------------- K6: GAT attention + aggregation ----------------
__global__ void __launch_bounds__(256) k_gat(const float* __restrict__ bgnn){
  __shared__ int   sidx[4][KK];
  __shared__ float stv[4][KK];
  __shared__ float sw[4][KK+1];
  int t = threadIdx.x;
  int g = t >> 6, d = t & 63;
  int row = blockIdx.x*4 + g;
  int b = row >> 10, i = row & (NN-1);
  if (d < KK){
    stv[g][d] = g_tv[row*KK + d];
    sidx[g][d] = g_ti[row*KK + d];
  }
  __syncthreads();
  if (d < 32){
    int lane = d;
    float si = g_si[row];
    float a;
    if (lane < KK){
      int j = sidx[g][lane];
      float sj = g_sj[b*NN + j];
      a = (j == i) ? -CUDART_INF_F : lrelu(si + sj);
    } else if (lane == KK){
      a = lrelu(si + g_sj[row]);
    } else a = -CUDART_INF_F;
    float m = a;
    #pragma unroll
    for (int off = 16; off > 0; off >>= 1) m = fmaxf(m, __shfl_xor_sync(0xffffffffu, m, off));
    float e = (lane <= KK) ? expf(a - m) : 0.f;
    float s = e;
    #pragma unroll
    for (int off = 16; off > 0; off >>= 1) s += __shfl_xor_sync(0xffffffffu, s, off);
    float att = e / s;
    float tvv = (lane < KK) ? stv[g][lane] : -CUDART_INF_F;
    float m2 = tvv;
    #pragma unroll
    for (int off = 16; off > 0; off >>= 1) m2 = fmaxf(m2, __shfl_xor_sync(0xffffffffu, m2, off));
    float e2 = (lane < KK) ? expf(tvv - m2) : 0.f;
    float s2 = e2;
    #pragma unroll
    for (int off = 16; off > 0; off >>= 1) s2 += __shfl_xor_sync(0xffffffffu, s2, off);
    if (lane <= KK)
      sw[g][lane] = (lane < KK) ? att * (e2 / s2) : att;
  }
  __syncthreads();
  float acc = sw[g][KK] * g_xlin[row*DD + d];
  #pragma unroll 4
  for (int k = 0; k < KK; k++)
    acc = fmaf(sw[g][k], g_xlin[((size_t)b*NN + sidx[g][k])*DD + d], acc);
  acc += bgnn[d];
  g_gnn[row*DD + d] = acc;
}

// ---------------- K7: BN1 stats ----------------
__global__ void __launch_bounds__(256) k_stats1(){
  __shared__ float ss[256], sq[256];
  int t = threadIdx.x;
  int c = t >> 6, d = t & 63;
  float s = 0.f, q = 0.f;
  int base = blockIdx.x * 256;
  for (int it = 0; it < 64; it++){
    int row = base + it*4 + c;
    float x = g_gnn[row*DD + d];
    s += x;
    q = fmaf(x, x, q);
  }
  ss[t] = s; sq[t] = q;
  __syncthreads();
  if (t < 64){
    double S = (double)ss[t] + ss[t+64] + ss[t+128] + ss[t+192];
    double Q = (double)sq[t] + sq[t+64] + sq[t+128] + sq[t+192];
    atomicAdd(&g_stats[d], S);
    atomicAdd(&g_stats[DD + d], Q);
  }
}

// ---------------- K8: apply BN1 + relu + embed-mul; BN2 stats ----------------
__global__ void __launch_bounds__(256) k_bn1mul(const float* __restrict__ g1,
    const float* __restrict__ be1, const float* __restrict__ net){
  __shared__ float ss[256], sq[256];
  int t = threadIdx.x;
  int c = t >> 6, d = t & 63;
  double inv = 1.0 / (double)NROWS;
  double mu = g_stats[d] * inv;
  double var = g_stats[DD + d] * inv - mu*mu;
  float scale = g1[d] * rsqrtf((float)var + BN_EPS);
  float shift = be1[d] - (float)mu * scale;
  float s = 0.f, q = 0.f;
  int base = blockIdx.x * 256;
  for (int it = 0; it < 64; it++){
    int row = base + it*4 + c;
    float x = g_gnn[row*DD + d];
    float gv = fmaf(x, scale, shift);
    gv = fmaxf(gv, 0.f);
    float y = gv * net[(row & (NN-1))*DD + d];
    g_y[row*DD + d] = y;
    s += y;
    q = fmaf(y, y, q);
  }
  ss[t] = s; sq[t] = q;
  __syncthreads();
  if (t < 64){
    double S = (double)ss[t] + ss[t+64] + ss[t+128] + ss[t+192];
    double Q = (double)sq[t] + sq[t+64] + sq[t+128] + sq[t+192];
    atomicAdd(&g_stats[2*DD + d], S);
    atomicAdd(&g_stats[3*DD + d], Q);
  }
}

// ---------------- K9: BN2 + relu + output head ----------------
__global__ void __launch_bounds__(256) k_head(const float* __restrict__ g2,
    const float* __restrict__ be2, const float* __restrict__ Wo,
    const float* __restrict__ bo, float* __restrict__ dout){
  int warp = threadIdx.x >> 5;
  int lane = threadIdx.x & 31;
  int row = blockIdx.x*8 + warp;
  double inv = 1.0 / (double)NROWS;
  float acc = 0.f;
  #pragma unroll
  for (int h = 0; h < 2; h++){
    int d = lane + h*32;
    double mu = g_stats[2*DD + d] * inv;
    double var = g_stats[3*DD + d] * inv - mu*mu;
    float scale = g2[d] * rsqrtf((float)var + BN_EPS);
    float shift = be2[d] - (float)mu * scale;
    float y = g_y[row*DD + d];
    float r = fmaxf(fmaf(y, scale, shift), 0.f);
    acc = fmaf(r, Wo[d], acc);
  }
  #pragma unroll
  for (int off = 16; off > 0; off >>= 1)
    acc += __shfl_down_sync(0xffffffffu, acc, off);
  if (lane == 0) dout[row] = acc + bo[0];
}

// ---------------- launch ----------------
extern "C" void kernel_launch(void* const* d_in, const int* in_sizes, int n_in,
                              void* d_out, int out_size) {
  const float* data   = (const float*)d_in[0];
  const float* gum    = (const float*)d_in[1];
  const float* Wc     = (const float*)d_in[2];
  const float* bc     = (const float*)d_in[3];
  const float* Wap    = (const float*)d_in[4];
  const float* bap    = (const float*)d_in[5];
  const float* Wav    = (const float*)d_in[6];
  const float* Wr     = (const float*)d_in[7];
  const float* br     = (const float*)d_in[8];
  const float* ebase  = (const float*)d_in[9];
  const float* lru    = (const float*)d_in[10];
  const float* lrv    = (const float*)d_in[11];
  const float* Wg     = (const float*)d_in[12];
  const float* ai     = (const float*)d_in[13];
  const float* aj     = (const float*)d_in[14];
  const float* aei    = (const float*)d_in[15];
  const float* aej    = (const float*)d_in[16];
  const float* bgnn   = (const float*)d_in[17];
  const float* g1     = (const float*)d_in[18];
  const float* be1    = (const float*)d_in[19];
  const float* net    = (const float*)d_in[20];
  const float* g2     = (const float*)d_in[21];
  const float* be2    = (const float*)d_in[22];
  const float* Wo     = (const float*)d_in[23];
  const float* bo     = (const float*)d_in[24];

  float* out    = (float*)d_out;              // [B,N]   32768
  float* hs_out = out + NROWS;                // [B,D]   2048
  float* ps_out = hs_out + BB*DD;             // [B,M]   128

  k_zero<<<1, 256>>>();
  k_cond<<<NROWS, 64>>>(data, Wc, bc, Wap, bap, Wav, Wg);
  k_pool<<<BB, 256>>>(Wr, br, gum, hs_out, ps_out);
  k_mixed<<<NROWS, 64>>>(ebase, lru, lrv, ai, aj, aei, aej);
  k_scores<<<dim3(16,16,32), 256>>>();
  k_topk<<<NROWS/8, 256>>>();
  k_gat<<<NROWS/4, 256>>>(bgnn);
  k_stats1<<<128, 256>>>();
  k_bn1mul<<<128, 256>>>(g1, be1, net);
  k_head<<<NROWS/8, 256>>>(g2, be2, Wo, bo, out);
}

// round 3
// speedup vs baseline: 1.2849x; 1.2849x over previous
#include <cuda_runtime.h>
#include <math_constants.h>
#include <math.h>

#define BB 32
#define NN 1024
#define FF 10
#define DD 64
#define MM 4
#define RR 8
#define KK 20
#define NROWS (BB*NN)           // 32768
#define BN_EPS 1e-5f

typedef unsigned long long ull;

// ---------------- scratch (device globals; no runtime allocation) ----------------
__device__ float g_hit[NROWS*DD];        // h_it  [B,N,D]
__device__ float g_xlin[NROWS*DD];       // x_lin [B,N,D]
__device__ float g_eit[NROWS];           // e_it  [B,N]
__device__ float g_pih[BB*MM];           // pi_hard (forward value of pi_t)
__device__ float g_proto[MM*NN*DD];      // expert prototypes [M,N,D]
__device__ float g_mixed[NROWS*DD];      // mixed [B,N,D]
__device__ float g_si[NROWS];
__device__ float g_sj[NROWS];
__device__ float g_scores[(size_t)BB*NN*NN];   // 128 MiB
__device__ float g_tv[NROWS*KK];
__device__ int   g_ti[NROWS*KK];
__device__ float g_gnn[NROWS*DD];
__device__ float g_y[NROWS*DD];
__device__ double g_stats[4*DD];         // sum1, sq1, sum2, sq2

// ---------------- helpers ----------------
__device__ __forceinline__ float nanfix(float x){
  if (isnan(x)) return 0.f;
  if (isinf(x)) return x > 0.f ? 1e4f : -1e4f;
  return x;
}
__device__ __forceinline__ float lrelu(float x){ return x >= 0.f ? x : 0.2f*x; }

__device__ __forceinline__ ull ffma2(ull a, ull b, ull c){
  ull d;
  asm("fma.rn.f32x2 %0, %1, %2, %3;" : "=l"(d) : "l"(a), "l"(b), "l"(c));
  return d;
}
__device__ __forceinline__ ull dup2(float a){
  ull r;
  asm("mov.b64 %0, {%1, %1};" : "=l"(r) : "f"(a));
  return r;
}
__device__ __forceinline__ void unpack2(ull v, float& lo, float& hi){
  asm("mov.b64 {%0, %1}, %2;" : "=f"(lo), "=f"(hi) : "l"(v));
}

// ---------------- K0: zero BN accumulators ----------------
__global__ void k_zero(){
  g_stats[threadIdx.x] = 0.0;
}

// ---------------- K1: cond MLP (h_it, e_it) + x_lin  (warp per row) ----------------
__global__ void __launch_bounds__(256) k_cond(const float* __restrict__ data,
    const float* __restrict__ Wc, const float* __restrict__ bc,
    const float* __restrict__ Wap, const float* __restrict__ bap,
    const float* __restrict__ Wav, const float* __restrict__ Wg){
  __shared__ float Wap_s[DD*DD];
  __shared__ float Wc_s[FF*DD];
  __shared__ float Wg_s[FF*DD];
  __shared__ float hbuf[8][DD];
  int t = threadIdx.x;
  for (int e = t; e < DD*DD; e += 256) Wap_s[e] = Wap[e];
  for (int e = t; e < FF*DD; e += 256){ Wc_s[e] = Wc[e]; Wg_s[e] = Wg[e]; }
  __syncthreads();
  int warp = t >> 5, lane = t & 31;
  int row = blockIdx.x*8 + warp;
  const float* dr = data + row*FF;
  float x[FF];
  #pragma unroll
  for (int f = 0; f < FF; f++) x[f] = dr[f];
  int d0 = lane, d1 = lane + 32;
  float h0 = bc[d0], h1 = bc[d1], xl0 = 0.f, xl1 = 0.f;
  #pragma unroll
  for (int f = 0; f < FF; f++){
    h0  = fmaf(x[f], Wc_s[f*DD+d0], h0);
    h1  = fmaf(x[f], Wc_s[f*DD+d1], h1);
    xl0 = fmaf(x[f], Wg_s[f*DD+d0], xl0);
    xl1 = fmaf(x[f], Wg_s[f*DD+d1], xl1);
  }
  g_hit[row*DD+d0] = h0;  g_hit[row*DD+d1] = h1;
  g_xlin[row*DD+d0] = xl0; g_xlin[row*DD+d1] = xl1;
  hbuf[warp][d0] = h0; hbuf[warp][d1] = h1;
  __syncwarp();
  float a0 = bap[d0], a1 = bap[d1];
  #pragma unroll 16
  for (int e = 0; e < DD; e++){
    float he = hbuf[warp][e];
    a0 = fmaf(he, Wap_s[e*DD+d0], a0);
    a1 = fmaf(he, Wap_s[e*DD+d1], a1);
  }
  a0 = lrelu(a0); a1 = lrelu(a1);
  float ts = a0*Wav[d0] + a1*Wav[d1];
  #pragma unroll
  for (int off = 16; off > 0; off >>= 1) ts += __shfl_xor_sync(0xffffffffu, ts, off);
  if (lane == 0) g_eit[row] = nanfix(ts);
}

// ---------------- K2: pooling softmax + h_sys + gumbel top-2 routing ----------------
__global__ void __launch_bounds__(256) k_pool(const float* __restrict__ Wr,
    const float* __restrict__ br, const float* __restrict__ gum,
    float* __restrict__ hs_out, float* __restrict__ ps_out){
  int b = blockIdx.x, t = threadIdx.x;
  __shared__ float red[256];
  __shared__ float swv[NN];
  __shared__ float shs[DD];
  __shared__ float slog[MM];
  const float* e = g_eit + b*NN;
  float m = -CUDART_INF_F;
  for (int n = t; n < NN; n += 256) m = fmaxf(m, e[n]);
  red[t] = m; __syncthreads();
  for (int s = 128; s > 0; s >>= 1){ if (t < s) red[t] = fmaxf(red[t], red[t+s]); __syncthreads(); }
  float mx = red[0];
  __syncthreads();
  float se = 0.f;
  for (int n = t; n < NN; n += 256){ float w = expf(e[n] - mx); swv[n] = w; se += w; }
  red[t] = se; __syncthreads();
  for (int s = 128; s > 0; s >>= 1){ if (t < s) red[t] += red[t+s]; __syncthreads(); }
  float denom = red[0];
  __syncthreads();
  int d = t & 63, c = t >> 6;
  float acc = 0.f;
  for (int n = c; n < NN; n += 4)
    acc = fmaf(swv[n], g_hit[((size_t)b*NN + n)*DD + d], acc);
  red[t] = acc; __syncthreads();
  if (t < DD){
    float hs = (red[t] + red[t+64] + red[t+128] + red[t+192]) / denom;
    shs[t] = hs;
    hs_out[b*DD + t] = hs;
  }
  __syncthreads();
  if (t < MM){
    float lg = br[t] + gum[b*MM + t];   // TAU = 1
    #pragma unroll 8
    for (int dd2 = 0; dd2 < DD; dd2++) lg = fmaf(shs[dd2], Wr[dd2*MM + t], lg);
    slog[t] = lg;
  }
  __syncthreads();
  if (t == 0){
    float mm = slog[0];
    #pragma unroll
    for (int i = 1; i < MM; i++) mm = fmaxf(mm, slog[i]);
    float p[MM]; float s = 0.f;
    #pragma unroll
    for (int i = 0; i < MM; i++){ p[i] = expf(slog[i] - mm); s += p[i]; }
    #pragma unroll
    for (int i = 0; i < MM; i++){ p[i] /= s; ps_out[b*MM + i] = p[i]; }
    int i1 = 0;
    #pragma unroll
    for (int i = 1; i < MM; i++) if (p[i] > p[i1]) i1 = i;
    int i2 = -1;
    #pragma unroll
    for (int i = 0; i < MM; i++){
      if (i == i1) continue;
      if (i2 < 0 || p[i] > p[i2]) i2 = i;
    }
    float nrm = fmaxf(p[i1] + p[i2], 1e-12f);
    #pragma unroll
    for (int i = 0; i < MM; i++) g_pih[b*MM + i] = 0.f;
    g_pih[b*MM + i1] = p[i1] / nrm;
    g_pih[b*MM + i2] = p[i2] / nrm;
  }
}

// ---------------- K3a: expert prototypes (pi-independent) ----------------
__global__ void __launch_bounds__(256) k_proto(const float* __restrict__ ebase,
    const float* __restrict__ lru, const float* __restrict__ lrv){
  int t = threadIdx.x, warp = t >> 5, lane = t & 31;
  int rown = blockIdx.x*8 + warp;        // m*NN + n
  int m = rown >> 10, n = rown & (NN-1);
  int d0 = lane, d1 = lane + 32;
  float p0 = ebase[n*DD+d0], p1 = ebase[n*DD+d1];
  #pragma unroll
  for (int r = 0; r < RR; r++){
    float u = lru[rown*RR + r];
    p0 = fmaf(u, lrv[(m*RR+r)*DD+d0], p0);
    p1 = fmaf(u, lrv[(m*RR+r)*DD+d1], p1);
  }
  g_proto[rown*DD+d0] = p0;
  g_proto[rown*DD+d1] = p1;
}

// ---------------- K3b: mixed = pi @ proto, + s_i / s_j ----------------
__global__ void __launch_bounds__(256) k_mixed(const float* __restrict__ ai,
    const float* __restrict__ aj, const float* __restrict__ aei,
    const float* __restrict__ aej){
  int t = threadIdx.x, warp = t >> 5, lane = t & 31;
  int row = blockIdx.x*8 + warp;
  int b = row >> 10, n = row & (NN-1);
  int d0 = lane, d1 = lane + 32;
  float pi0 = g_pih[b*MM+0], pi1 = g_pih[b*MM+1];
  float pi2 = g_pih[b*MM+2], pi3 = g_pih[b*MM+3];
  float mx0, mx1;
  {
    const float* p0 = g_proto + (0*NN+n)*DD;
    const float* p1 = g_proto + (1*NN+n)*DD;
    const float* p2 = g_proto + (2*NN+n)*DD;
    const float* p3 = g_proto + (3*NN+n)*DD;
    mx0 = pi0*p0[d0] + pi1*p1[d0] + pi2*p2[d0] + pi3*p3[d0];
    mx1 = pi0*p0[d1] + pi1*p1[d1] + pi2*p2[d1] + pi3*p3[d1];
  }
  mx0 = nanfix(mx0); mx1 = nanfix(mx1);
  g_mixed[row*DD+d0] = mx0;
  g_mixed[row*DD+d1] = mx1;
  float xl0 = g_xlin[row*DD+d0], xl1 = g_xlin[row*DD+d1];
  float r1 = xl0*ai[d0] + mx0*aei[d0] + xl1*ai[d1] + mx1*aei[d1];
  float r2 = xl0*aj[d0] + mx0*aej[d0] + xl1*aj[d1] + mx1*aej[d1];
  #pragma unroll
  for (int off = 16; off > 0; off >>= 1){
    r1 += __shfl_xor_sync(0xffffffffu, r1, off);
    r2 += __shfl_xor_sync(0xffffffffu, r2, off);
  }
  if (lane == 0){ g_si[row] = r1; g_sj[row] = r2; }
}

// ---------------- K4: scores = mixed @ mixed^T, symmetric, f32x2, 128x128 tiles ----------------
__global__ void __launch_bounds__(256, 2) k_scores(){
  extern __shared__ float smem[];
  float* Ast = smem;               // [64][132]  (k-major, i contiguous)
  float* Bst = smem + 64*132;      // [64][132]
  int b = blockIdx.z;
  int p = blockIdx.x, ti = 0;
  while (p >= 8 - ti){ p -= 8 - ti; ti++; }
  int tj = ti + p;
  int bi = ti*128, bj = tj*128;
  int t = threadIdx.x;
  const float* A  = g_mixed + ((size_t)b*NN + bi)*DD;
  const float* Bm = g_mixed + ((size_t)b*NN + bj)*DD;
  {
    int i = t >> 1, kh = (t & 1) * 32;
    const float4* a4 = (const float4*)(A  + i*DD + kh);
    const float4* b4 = (const float4*)(Bm + i*DD + kh);
    #pragma unroll
    for (int q = 0; q < 8; q++){
      float4 av = a4[q], bv = b4[q];
      int k = kh + q*4;
      Ast[(k+0)*132 + i] = av.x; Ast[(k+1)*132 + i] = av.y;
      Ast[(k+2)*132 + i] = av.z; Ast[(k+3)*132 + i] = av.w;
      Bst[(k+0)*132 + i] = bv.x; Bst[(k+1)*132 + i] = bv.y;
      Bst[(k+2)*132 + i] = bv.z; Bst[(k+3)*132 + i] = bv.w;
    }
  }
  __syncthreads();
  int tx = t & 15, ty = t >> 4;
  int i0 = ty*8, j0 = tx*8;
  ull acc[8][4];
  #pragma unroll
  for (int ii = 0; ii < 8; ii++)
    #pragma unroll
    for (int jj = 0; jj < 4; jj++) acc[ii][jj] = 0ull;
  #pragma unroll 16
  for (int k = 0; k < 64; k++){
    const float* ar = Ast + k*132 + i0;
    float4 aA = *(const float4*)ar;
    float4 aB = *(const float4*)(ar + 4);
    const ulonglong2* brp = (const ulonglong2*)(Bst + k*132 + j0);
    ulonglong2 b03 = brp[0];
    ulonglong2 b47 = brp[1];
    float av[8] = {aA.x, aA.y, aA.z, aA.w, aB.x, aB.y, aB.z, aB.w};
    #pragma unroll
    for (int ii = 0; ii < 8; ii++){
      ull ad = dup2(av[ii]);
      acc[ii][0] = ffma2(ad, b03.x, acc[ii][0]);
      acc[ii][1] = ffma2(ad, b03.y, acc[ii][1]);
      acc[ii][2] = ffma2(ad, b47.x, acc[ii][2]);
      acc[ii][3] = ffma2(ad, b47.y, acc[ii][3]);
    }
  }
  size_t base = ((size_t)b*NN + bi + i0)*NN + bj + j0;
  #pragma unroll
  for (int ii = 0; ii < 8; ii++){
    ulonglong2* C = (ulonglong2*)(g_scores + base + (size_t)ii*NN);
    C[0] = make_ulonglong2(acc[ii][0], acc[ii][1]);
    C[1] = make_ulonglong2(acc[ii][2], acc[ii][3]);
  }
  if (ti != tj){
    float v[8][8];
    #pragma unroll
    for (int ii = 0; ii < 8; ii++)
      #pragma unroll
      for (int jp = 0; jp < 4; jp++)
        unpack2(acc[ii][jp], v[ii][2*jp], v[ii][2*jp+1]);
    size_t tb = ((size_t)b*NN + bj + j0)*NN + bi + i0;
    #pragma unroll
    for (int jj = 0; jj < 8; jj++){
      float4* C2 = (float4*)(g_scores + tb + (size_t)jj*NN);
      C2[0] = make_float4(v[0][jj], v[1][jj], v[2][jj], v[3][jj]);
      C2[1] = make_float4(v[4][jj], v[5][jj], v[6][jj], v[7][jj]);
    }
  }
}

// ---------------- K5: top-20 per row (warp per row, vectorized loads) ----------------
// slot s (0..31) of a lane maps to global j = (s>>2)*128 + lane*4 + (s&3);
// ascending s == ascending j per lane, so tie-breaks match lax.top_k.
__global__ void __launch_bounds__(256) k_topk(){
  int warp = threadIdx.x >> 5, lane = threadIdx.x & 31;
  int row = blockIdx.x*8 + warp;
  const float4* srow = (const float4*)(g_scores + (size_t)row*NN);
  float v[32];
  #pragma unroll
  for (int c = 0; c < 8; c++){
    float4 q = srow[c*32 + lane];
    v[c*4+0] = q.x; v[c*4+1] = q.y; v[c*4+2] = q.z; v[c*4+3] = q.w;
  }
  float c0v = -CUDART_INF_F, c1v = -CUDART_INF_F, c2v = -CUDART_INF_F;
  int c0s = 0, c1s = 0, c2s = 0;
  #pragma unroll
  for (int s = 0; s < 32; s++){
    float x = v[s];
    if (x > c2v){
      if (x > c1v){
        c2v = c1v; c2s = c1s;
        if (x > c0v){ c1v = c0v; c1s = c0s; c0v = x; c0s = s; }
        else        { c1v = x; c1s = s; }
      } else { c2v = x; c2s = s; }
    }
  }
  unsigned used = 0u;
  int p = 0;
  int cs = c0s;
  float candv = c0v;
  int candg = ((c0s >> 2) << 7) + (lane << 2) + (c0s & 3);
  float* otv = g_tv + row*KK;
  int*   oti = g_ti + row*KK;
  for (int k = 0; k < KK; k++){
    float bv = candv; int bg = candg;
    #pragma unroll
    for (int off = 16; off > 0; off >>= 1){
      float ov = __shfl_xor_sync(0xffffffffu, bv, off);
      int   og = __shfl_xor_sync(0xffffffffu, bg, off);
      if (ov > bv || (ov == bv && og < bg)){ bv = ov; bg = og; }
    }
    if (lane == 0){ otv[k] = bv; oti[k] = bg; }
    if (bg == candg){
      used |= 1u << cs;
      p++;
      if (p == 1){ cs = c1s; candv = c1v; candg = ((c1s>>2)<<7) + (lane<<2) + (c1s&3); }
      else if (p == 2){ cs = c2s; candv = c2v; candg = ((c2s>>2)<<7) + (lane<<2) + (c2s&3); }
      else {
        candv = -CUDART_INF_F; cs = -1;
        #pragma unroll
        for (int s = 0; s < 32; s++){
          if (!((used >> s) & 1u)){
            float x = v[s];
            if (x > candv){ candv = x; cs = s; }
          }
        }
        candg = (cs >= 0) ? (((cs>>2)<<7) + (lane<<2) + (cs&3)) : (1<<20) + lane;
      }
    }
  }
}

// ---------------- K6: GAT attention + aggregation ----------------
__global__ void __launch_bounds__(256) k_gat(const float* __restrict__ bgnn){
  __shared__ int   sidx[4][KK];
  __shared__ float stv[4][KK];
  __shared__ float sw[4][KK+1];
  int t = threadIdx.x;
  int g = t >> 6, d = t & 63;
  int row = blockIdx.x*4 + g;
  int b = row >> 10, i = row & (NN-1);
  if (d < KK){
    stv[g][d] = g_tv[row*KK + d];
    sidx[g][d] = g_ti[row*KK + d];
  }
  __syncthreads();
  if (d < 32){
    int lane = d;
    float si = g_si[row];
    float a;
    if (lane < KK){
      int j = sidx[g][lane];
      float sj = g_sj[b*NN + j];
      a = (j == i) ? -CUDART_INF_F : lrelu(si + sj);
    } else if (lane == KK){
      a = lrelu(si + g_sj[row]);
    } else a = -CUDART_INF_F;
    float m = a;
    #pragma unroll
    for (int off = 16; off > 0; off >>= 1) m = fmaxf(m, __shfl_xor_sync(0xffffffffu, m, off));
    float e = (lane <= KK) ? expf(a - m) : 0.f;
    float s = e;
    #pragma unroll
    for (int off = 16; off > 0; off >>= 1) s += __shfl_xor_sync(0xffffffffu, s, off);
    float att = e / s;
    float tvv = (lane < KK) ? stv[g][lane] : -CUDART_INF_F;
    float m2 = tvv;
    #pragma unroll
    for (int off = 16; off > 0; off >>= 1) m2 = fmaxf(m2, __shfl_xor_sync(0xffffffffu, m2, off));
    float e2 = (lane < KK) ? expf(tvv - m2) : 0.f;
    float s2 = e2;
    #pragma unroll
    for (int off = 16; off > 0; off >>= 1) s2 += __shfl_xor_sync(0xffffffffu, s2, off);
    if (lane <= KK)
      sw[g][lane] = (lane < KK) ? att * (e2 / s2) : att;
  }
  __syncthreads();
  float acc = sw[g][KK] * g_xlin[row*DD + d];
  #pragma unroll 4
  for (int k = 0; k < KK; k++)
    acc = fmaf(sw[g][k], g_xlin[((size_t)b*NN + sidx[g][k])*DD + d], acc);
  acc += bgnn[d];
  g_gnn[row*DD + d] = acc;
}

// ---------------- K7: BN1 stats ----------------
__global__ void __launch_bounds__(256) k_stats1(){
  __shared__ float ss[256], sq[256];
  int t = threadIdx.x;
  int c = t >> 6, d = t & 63;
  float s = 0.f, q = 0.f;
  int base = blockIdx.x * 256;
  for (int it = 0; it < 64; it++){
    int row = base + it*4 + c;
    float x = g_gnn[row*DD + d];
    s += x;
    q = fmaf(x, x, q);
  }
  ss[t] = s; sq[t] = q;
  __syncthreads();
  if (t < 64){
    double S = (double)ss[t] + ss[t+64] + ss[t+128] + ss[t+192];
    double Q = (double)sq[t] + sq[t+64] + sq[t+128] + sq[t+192];
    atomicAdd(&g_stats[d], S);
    atomicAdd(&g_stats[DD + d], Q);
  }
}

// ---------------- K8: apply BN1 + relu + embed-mul; BN2 stats ----------------
__global__ void __launch_bounds__(256) k_bn1mul(const float* __restrict__ g1,
    const float* __restrict__ be1, const float* __restrict__ net){
  __shared__ float ss[256], sq[256];
  int t = threadIdx.x;
  int c = t >> 6, d = t & 63;
  double inv = 1.0 / (double)NROWS;
  double mu = g_stats[d] * inv;
  double var = g_stats[DD + d] * inv - mu*mu;
  float scale = g1[d] * rsqrtf((float)var + BN_EPS);
  float shift = be1[d] - (float)mu * scale;
  float s = 0.f, q = 0.f;
  int base = blockIdx.x * 256;
  for (int it = 0; it < 64; it++){
    int row = base + it*4 + c;
    float x = g_gnn[row*DD + d];
    float gv = fmaf(x, scale, shift);
    gv = fmaxf(gv, 0.f);
    float y = gv * net[(row & (NN-1))*DD + d];
    g_y[row*DD + d] = y;
    s += y;
    q = fmaf(y, y, q);
  }
  ss[t] = s; sq[t] = q;
  __syncthreads();
  if (t < 64){
    double S = (double)ss[t] + ss[t+64] + ss[t+128] + ss[t+192];
    double Q = (double)sq[t] + sq[t+64] + sq[t+128] + sq[t+192];
    atomicAdd(&g_stats[2*DD + d], S);
    atomicAdd(&g_stats[3*DD + d], Q);
  }
}

// ---------------- K9: BN2 + relu + output head ----------------
__global__ void __launch_bounds__(256) k_head(const float* __restrict__ g2,
    const float* __restrict__ be2, const float* __restrict__ Wo,
    const float* __restrict__ bo, float* __restrict__ dout){
  int warp = threadIdx.x >> 5;
  int lane = threadIdx.x & 31;
  int row = blockIdx.x*8 + warp;
  double inv = 1.0 / (double)NROWS;
  float acc = 0.f;
  #pragma unroll
  for (int h = 0; h < 2; h++){
    int d = lane + h*32;
    double mu = g_stats[2*DD + d] * inv;
    double var = g_stats[3*DD + d] * inv - mu*mu;
    float scale = g2[d] * rsqrtf((float)var + BN_EPS);
    float shift = be2[d] - (float)mu * scale;
    float y = g_y[row*DD + d];
    float r = fmaxf(fmaf(y, scale, shift), 0.f);
    acc = fmaf(r, Wo[d], acc);
  }
  #pragma unroll
  for (int off = 16; off > 0; off >>= 1)
    acc += __shfl_down_sync(0xffffffffu, acc, off);
  if (lane == 0) dout[row] = acc + bo[0];
}

// ---------------- launch ----------------
extern "C" void kernel_launch(void* const* d_in, const int* in_sizes, int n_in,
                              void* d_out, int out_size) {
  const float* data   = (const float*)d_in[0];
  const float* gum    = (const float*)d_in[1];
  const float* Wc     = (const float*)d_in[2];
  const float* bc     = (const float*)d_in[3];
  const float* Wap    = (const float*)d_in[4];
  const float* bap    = (const float*)d_in[5];
  const float* Wav    = (const float*)d_in[6];
  const float* Wr     = (const float*)d_in[7];
  const float* br     = (const float*)d_in[8];
  const float* ebase  = (const float*)d_in[9];
  const float* lru    = (const float*)d_in[10];
  const float* lrv    = (const float*)d_in[11];
  const float* Wg     = (const float*)d_in[12];
  const float* ai     = (const float*)d_in[13];
  const float* aj     = (const float*)d_in[14];
  const float* aei    = (const float*)d_in[15];
  const float* aej    = (const float*)d_in[16];
  const float* bgnn   = (const float*)d_in[17];
  const float* g1     = (const float*)d_in[18];
  const float* be1    = (const float*)d_in[19];
  const float* net    = (const float*)d_in[20];
  const float* g2     = (const float*)d_in[21];
  const float* be2    = (const float*)d_in[22];
  const float* Wo     = (const float*)d_in[23];
  const float* bo     = (const float*)d_in[24];

  float* out    = (float*)d_out;              // [B,N]   32768
  float* hs_out = out + NROWS;                // [B,D]   2048
  float* ps_out = hs_out + BB*DD;             // [B,M]   128

  const int SC_SMEM = 2*64*132*4;             // 67584 B
  cudaFuncSetAttribute(k_scores, cudaFuncAttributeMaxDynamicSharedMemorySize, SC_SMEM);

  k_zero<<<1, 256>>>();
  k_cond<<<NROWS/8, 256>>>(data, Wc, bc, Wap, bap, Wav, Wg);
  k_proto<<<MM*NN/8, 256>>>(ebase, lru, lrv);
  k_pool<<<BB, 256>>>(Wr, br, gum, hs_out, ps_out);
  k_mixed<<<NROWS/8, 256>>>(ai, aj, aei, aej);
  k_scores<<<dim3(36, 1, BB), 256, SC_SMEM>>>();
  k_topk<<<NROWS/8, 256>>>();
  k_gat<<<NROWS/4, 256>>>(bgnn);
  k_stats1<<<128, 256>>>();
  k_bn1mul<<<128, 256>>>(g1, be1, net);
  k_head<<<NROWS/8, 256>>>(g2, be2, Wo, bo, out);
}